// round 1
// baseline (speedup 1.0000x reference)
#include <cuda_runtime.h>
#include <cuda_bf16.h>
#include <cstdio>

// Problem constants
#define BB 256      // batch
#define TT 15       // timesteps
#define LL 6        // layers
#define UU 1000     // hidden units
#define EE 1024     // embedding dim
#define VV 32000    // vocab
#define U3 3000     // 3*U
#define BT (BB*TT)  // 3840

// ---------------------------------------------------------------------------
// Scratch (static device globals; no allocation at runtime)
// ---------------------------------------------------------------------------
__device__ float g_emb[(size_t)BT * EE];            // [3840,1024]
__device__ float g_xpre[(size_t)LL * BT * U3];      // [6][3840][3000]
__device__ float g_mh[(size_t)LL * BB * U3];        // per-wavefront cell mh
__device__ float g_mx[(size_t)LL * BB * U3];        // per-wavefront cell mx
__device__ float g_buf[(size_t)2 * LL * BB * UU];   // double-buffered hidden states
__device__ float g_final[(size_t)BB * LL * UU];     // [256,6000]

// ---------------------------------------------------------------------------
// Embedding gather: g_emb[b*T+t, :] = table[tokens[b*T+t], :]
// ---------------------------------------------------------------------------
__global__ void embed_kernel(const int* __restrict__ tokens,
                             const float* __restrict__ table)
{
    long idx = (long)blockIdx.x * blockDim.x + threadIdx.x;   // over BT*E/4
    long total = (long)BT * (EE / 4);
    if (idx >= total) return;
    long row = idx / (EE / 4);
    long c4  = idx - row * (EE / 4);
    int tok = tokens[row];
    ((float4*)g_emb)[row * (EE / 4) + c4] =
        ((const float4*)table)[(long)tok * (EE / 4) + c4];
}

// ---------------------------------------------------------------------------
// 128x128x8 fp32 SGEMM, job-batched via blockIdx.z.
// A row-major [M,K] lda, B row-major [K,N] ldb, C row-major [M,N] ldc.
// Requires: M % 128 == 0, K % 8 == 0, all row strides 16B aligned. N guarded.
// ---------------------------------------------------------------------------
struct GemmJobs {
    const float* A[12];
    const float* B[12];
    float*       C[12];
};

__global__ __launch_bounds__(256) void sgemm_kernel(
    GemmJobs jobs, int M, int N, int K, int lda, int ldb, int ldc)
{
    const float* A  = jobs.A[blockIdx.z];
    const float* Bm = jobs.B[blockIdx.z];
    float*       C  = jobs.C[blockIdx.z];

    __shared__ float As[8][128];
    __shared__ float Bs[8][128];

    int tid = threadIdx.x;
    int m0 = blockIdx.y * 128;
    int n0 = blockIdx.x * 128;

    int arow = tid >> 1;           // 0..127
    int acol = (tid & 1) * 4;      // 0 or 4
    int brow = tid >> 5;           // 0..7
    int bcol = (tid & 31) * 4;     // 0..124

    int tx = tid & 15;
    int ty = tid >> 4;

    float acc[8][8];
#pragma unroll
    for (int i = 0; i < 8; i++)
#pragma unroll
        for (int j = 0; j < 8; j++) acc[i][j] = 0.f;

    const float* Aptr = A + (long)(m0 + arow) * lda + acol;
    const float* Bptr = Bm + (long)brow * ldb + n0 + bcol;
    bool bfull = (n0 + 128 <= N);

    for (int k0 = 0; k0 < K; k0 += 8) {
        float4 av = *(const float4*)(Aptr + k0);
        As[acol + 0][arow] = av.x;
        As[acol + 1][arow] = av.y;
        As[acol + 2][arow] = av.z;
        As[acol + 3][arow] = av.w;

        if (bfull) {
            float4 bv = *(const float4*)(Bptr + (long)k0 * ldb);
            *(float4*)&Bs[brow][bcol] = bv;
        } else {
#pragma unroll
            for (int j = 0; j < 4; j++) {
                int col = n0 + bcol + j;
                Bs[brow][bcol + j] = (col < N) ? Bptr[(long)k0 * ldb + j] : 0.f;
            }
        }
        __syncthreads();

#pragma unroll
        for (int kk = 0; kk < 8; kk++) {
            float a[8], b[8];
#pragma unroll
            for (int i = 0; i < 8; i++) a[i] = As[kk][ty * 8 + i];
#pragma unroll
            for (int j = 0; j < 8; j++) b[j] = Bs[kk][tx * 8 + j];
#pragma unroll
            for (int i = 0; i < 8; i++)
#pragma unroll
                for (int j = 0; j < 8; j++) acc[i][j] += a[i] * b[j];
        }
        __syncthreads();
    }

#pragma unroll
    for (int i = 0; i < 8; i++) {
        int m = m0 + ty * 8 + i;
#pragma unroll
        for (int j = 0; j < 8; j += 4) {
            int n = n0 + tx * 8 + j;
            if (n + 3 < N) {
                float4 v = make_float4(acc[i][j], acc[i][j + 1],
                                       acc[i][j + 2], acc[i][j + 3]);
                *(float4*)&C[(long)m * ldc + n] = v;
            } else {
#pragma unroll
                for (int jj = 0; jj < 4; jj++)
                    if (n + jj < N) C[(long)m * ldc + n + jj] = acc[i][j + jj];
            }
        }
    }
}

// ---------------------------------------------------------------------------
// GRU gate fusion per wavefront cell
// ---------------------------------------------------------------------------
struct WaveCells { int t[6]; int l[6]; };

__global__ void gate_kernel(WaveCells wc,
                            const float* __restrict__ bias_in,
                            const float* __restrict__ bias_rec)
{
    int c   = blockIdx.y;
    int idx = blockIdx.x * blockDim.x + threadIdx.x;
    if (idx >= BB * UU) return;
    int b = idx / UU;
    int u = idx - b * UU;
    int t = wc.t[c], l = wc.l[c];

    const float* xp = g_xpre + ((long)l * BT + (long)b * TT + t) * U3;
    float xz = xp[u]          + bias_in[l * U3 + u];
    float xr = xp[UU + u]     + bias_in[l * U3 + UU + u];
    float xh = xp[2 * UU + u] + bias_in[l * U3 + 2 * UU + u];

    const float* mh = g_mh + (long)c * BB * U3 + (long)b * U3;
    float hz = mh[u]          + bias_rec[l * U3 + u];
    float hr = mh[UU + u]     + bias_rec[l * U3 + UU + u];
    float hh = mh[2 * UU + u] + bias_rec[l * U3 + 2 * UU + u];

    if (l > 0) {
        const float* mx = g_mx + (long)c * BB * U3 + (long)b * U3;
        xz += mx[u];
        xr += mx[UU + u];
        xh += mx[2 * UU + u];
    }

    float h_old = g_buf[((((t + 1) & 1) * LL + l) * (long)BB + b) * UU + u];

    float z = 1.f / (1.f + expf(-(xz + hz)));
    float r = 1.f / (1.f + expf(-(xr + hr)));
    float cand = tanhf(xh + r * hh);
    float h_new = z * h_old + (1.f - z) * cand;

    g_buf[(((t & 1) * LL + l) * (long)BB + b) * UU + u] = h_new;
}

// ---------------------------------------------------------------------------
// Pack final hidden states [L][B][U] (parity 0) -> [B, L*U]
// ---------------------------------------------------------------------------
__global__ void pack_kernel()
{
    long idx = (long)blockIdx.x * blockDim.x + threadIdx.x;
    if (idx >= (long)BB * LL * UU) return;
    int b = (int)(idx / (LL * UU));
    int k = (int)(idx - (long)b * (LL * UU));
    int l = k / UU;
    int u = k - l * UU;
    g_final[idx] = g_buf[((0 * LL + l) * (long)BB + b) * UU + u];
}

// ---------------------------------------------------------------------------
// Row softmax with bias, in place on d_out [256, 32000]
// ---------------------------------------------------------------------------
__global__ void softmax_kernel(float* __restrict__ out,
                               const float* __restrict__ bias)
{
    int row = blockIdx.x;
    float* p = out + (long)row * VV;
    __shared__ float red[256];
    int tid = threadIdx.x;

    float m = -1e30f;
    for (int i = tid; i < VV; i += 256) m = fmaxf(m, p[i] + bias[i]);
    red[tid] = m; __syncthreads();
    for (int s = 128; s > 0; s >>= 1) {
        if (tid < s) red[tid] = fmaxf(red[tid], red[tid + s]);
        __syncthreads();
    }
    m = red[0]; __syncthreads();

    float sum = 0.f;
    for (int i = tid; i < VV; i += 256) {
        float e = expf(p[i] + bias[i] - m);
        p[i] = e;
        sum += e;
    }
    red[tid] = sum; __syncthreads();
    for (int s = 128; s > 0; s >>= 1) {
        if (tid < s) red[tid] += red[tid + s];
        __syncthreads();
    }
    float inv = 1.f / red[0];
    for (int i = tid; i < VV; i += 256) p[i] *= inv;
}

// ---------------------------------------------------------------------------
// Host driver
// ---------------------------------------------------------------------------
extern "C" void kernel_launch(void* const* d_in, const int* in_sizes, int n_in,
                              void* d_out, int out_size)
{
    const int*   tokens       = (const int*)  d_in[0];
    const float* init_states  = (const float*)d_in[1];
    const float* emb_table    = (const float*)d_in[2];
    const float* kernel0      = (const float*)d_in[3];
    const float* kernels_rest = (const float*)d_in[4];
    const float* rec_kernels  = (const float*)d_in[5];
    const float* bias_in      = (const float*)d_in[6];
    const float* bias_rec     = (const float*)d_in[7];
    const float* dense_kernel = (const float*)d_in[8];
    const float* dense_bias   = (const float*)d_in[9];
    float* out = (float*)d_out;

    float *p_emb, *p_xpre, *p_mh, *p_mx, *p_buf, *p_final;
    cudaGetSymbolAddress((void**)&p_emb,   g_emb);
    cudaGetSymbolAddress((void**)&p_xpre,  g_xpre);
    cudaGetSymbolAddress((void**)&p_mh,    g_mh);
    cudaGetSymbolAddress((void**)&p_mx,    g_mx);
    cudaGetSymbolAddress((void**)&p_buf,   g_buf);
    cudaGetSymbolAddress((void**)&p_final, g_final);

    // 1. embedding gather
    {
        long total = (long)BT * (EE / 4);
        embed_kernel<<<(unsigned)((total + 255) / 256), 256>>>(tokens, emb_table);
    }

    // 2. initial hidden states -> parity-1 buffer ([L][B][U] layout matches)
    cudaMemcpyAsync(p_buf + (size_t)LL * BB * UU, init_states,
                    (size_t)LL * BB * UU * sizeof(float),
                    cudaMemcpyDeviceToDevice, 0);

    // 3. Xpre[l] = emb @ Kx_l  for all 6 layers (batched, z = layer)
    {
        GemmJobs jb;
        for (int l = 0; l < LL; l++) {
            jb.A[l] = p_emb;
            jb.B[l] = (l == 0) ? kernel0
                               : kernels_rest + (size_t)(l - 1) * (EE + UU) * U3;
            jb.C[l] = p_xpre + (size_t)l * BT * U3;
        }
        dim3 grid((U3 + 127) / 128, BT / 128, LL);
        sgemm_kernel<<<grid, 256>>>(jb, BT, U3, EE, EE, U3, U3);
    }

    // 4. wavefront scan over cells (t,l) with t+l = w
    for (int w = 0; w < TT + LL - 1; w++) {
        GemmJobs jb;
        WaveCells wc;
        int nj = 0, nc = 0;
        int t_lo = (w - (LL - 1) > 0) ? (w - (LL - 1)) : 0;
        int t_hi = (w < TT - 1) ? w : (TT - 1);
        for (int t = t_lo; t <= t_hi; t++) {
            int l = w - t;
            int c = nc;
            wc.t[c] = t; wc.l[c] = l;
            // mh = h_prev(t-1,l) @ R_l
            jb.A[nj] = p_buf + ((size_t)((t + 1) & 1) * LL + l) * BB * UU;
            jb.B[nj] = rec_kernels + (size_t)l * UU * U3;
            jb.C[nj] = p_mh + (size_t)c * BB * U3;
            nj++;
            if (l > 0) {
                // mx = h(t, l-1) @ Kh_{l}
                jb.A[nj] = p_buf + ((size_t)(t & 1) * LL + (l - 1)) * BB * UU;
                jb.B[nj] = kernels_rest + (size_t)(l - 1) * (EE + UU) * U3
                                        + (size_t)EE * U3;
                jb.C[nj] = p_mx + (size_t)c * BB * U3;
                nj++;
            }
            nc++;
        }
        dim3 ggrid((U3 + 127) / 128, BB / 128, nj);
        sgemm_kernel<<<ggrid, 256>>>(jb, BB, U3, UU, UU, U3, U3);

        dim3 fgrid((BB * UU + 255) / 256, nc);
        gate_kernel<<<fgrid, 256>>>(wc, bias_in, bias_rec);
    }

    // 5. pack final hidden states -> [256, 6000]
    {
        long total = (long)BB * LL * UU;
        pack_kernel<<<(unsigned)((total + 255) / 256), 256>>>();
    }

    // 6. logits = final @ dense_kernel  (bias added in softmax)
    {
        GemmJobs jb;
        jb.A[0] = p_final;
        jb.B[0] = dense_kernel;
        jb.C[0] = out;
        dim3 grid(VV / 128, BB / 128, 1);
        sgemm_kernel<<<grid, 256>>>(jb, BB, VV, LL * UU, LL * UU, VV, VV);
    }

    // 7. softmax rows
    softmax_kernel<<<BB, 256>>>(out, dense_bias);
}

// round 13
// speedup vs baseline: 1.6537x; 1.6537x over previous
#include <cuda_runtime.h>
#include <cuda_bf16.h>
#include <cstdint>

// Problem constants
#define BB 256      // batch
#define TT 15       // timesteps
#define LL 6        // layers
#define UU 1000     // hidden units
#define EE 1024     // embedding dim
#define VV 32000    // vocab
#define U3 3000     // 3*U
#define BT (BB*TT)  // 3840

// ---------------------------------------------------------------------------
// Scratch (static device globals; no allocation at runtime)
// ---------------------------------------------------------------------------
__device__ float g_emb[(size_t)BT * EE];            // [3840,1024]
__device__ float g_xpre[(size_t)LL * BT * U3];      // [6][3840][3000]
__device__ float g_mh[(size_t)LL * BB * U3];        // per-wavefront cell mh
__device__ float g_mx[(size_t)LL * BB * U3];        // per-wavefront cell mx
__device__ float g_buf[(size_t)2 * LL * BB * UU];   // double-buffered hidden states
__device__ float g_final[(size_t)BB * LL * UU];     // [256,6000]

// ---------------------------------------------------------------------------
// Embedding gather
// ---------------------------------------------------------------------------
__global__ void embed_kernel(const int* __restrict__ tokens,
                             const float* __restrict__ table)
{
    long idx = (long)blockIdx.x * blockDim.x + threadIdx.x;
    long total = (long)BT * (EE / 4);
    if (idx >= total) return;
    long row = idx / (EE / 4);
    long c4  = idx - row * (EE / 4);
    int tok = tokens[row];
    ((float4*)g_emb)[row * (EE / 4) + c4] =
        ((const float4*)table)[(long)tok * (EE / 4) + c4];
}

// ---------------------------------------------------------------------------
// Tensor-core GEMM: fp32 in/out via bf16x3 split (hi*hi + hi*lo + lo*hi).
// C[M,N] = A[M,K] @ B[K,N], all row-major fp32.
// CTA tile 128x128x32, 8 warps, warp tile 64x32, mma.m16n8k16.bf16.
// Requires M%128==0, K%4==0, N%4==0, 16B-aligned row strides.
// ---------------------------------------------------------------------------
struct GemmJobs {
    const float* A[12];
    const float* B[12];
    float*       C[12];
};

__device__ __forceinline__ void ldmatrix_x4(uint32_t r[4], uint32_t addr) {
    asm volatile("ldmatrix.sync.aligned.m8n8.x4.shared.b16 {%0,%1,%2,%3}, [%4];"
                 : "=r"(r[0]), "=r"(r[1]), "=r"(r[2]), "=r"(r[3]) : "r"(addr));
}
__device__ __forceinline__ void ldmatrix_x2t(uint32_t r[2], uint32_t addr) {
    asm volatile("ldmatrix.sync.aligned.m8n8.x2.trans.shared.b16 {%0,%1}, [%2];"
                 : "=r"(r[0]), "=r"(r[1]) : "r"(addr));
}
__device__ __forceinline__ void mma_bf16(float c[4], const uint32_t a[4],
                                         const uint32_t b[2]) {
    asm volatile(
        "mma.sync.aligned.m16n8k16.row.col.f32.bf16.bf16.f32 "
        "{%0,%1,%2,%3}, {%4,%5,%6,%7}, {%8,%9}, {%0,%1,%2,%3};"
        : "+f"(c[0]), "+f"(c[1]), "+f"(c[2]), "+f"(c[3])
        : "r"(a[0]), "r"(a[1]), "r"(a[2]), "r"(a[3]), "r"(b[0]), "r"(b[1]));
}

__device__ __forceinline__ uint32_t pack_bf16(__nv_bfloat16 x, __nv_bfloat16 y) {
    return (uint32_t)__bfloat16_as_ushort(x) |
           ((uint32_t)__bfloat16_as_ushort(y) << 16);
}

// float4 -> 4 hi bf16 (uint2) + 4 lo bf16 (uint2)
__device__ __forceinline__ void split4(float4 f, uint2& hi, uint2& lo) {
    __nv_bfloat16 h0 = __float2bfloat16_rn(f.x);
    __nv_bfloat16 h1 = __float2bfloat16_rn(f.y);
    __nv_bfloat16 h2 = __float2bfloat16_rn(f.z);
    __nv_bfloat16 h3 = __float2bfloat16_rn(f.w);
    __nv_bfloat16 l0 = __float2bfloat16_rn(f.x - __bfloat162float(h0));
    __nv_bfloat16 l1 = __float2bfloat16_rn(f.y - __bfloat162float(h1));
    __nv_bfloat16 l2 = __float2bfloat16_rn(f.z - __bfloat162float(h2));
    __nv_bfloat16 l3 = __float2bfloat16_rn(f.w - __bfloat162float(h3));
    hi.x = pack_bf16(h0, h1); hi.y = pack_bf16(h2, h3);
    lo.x = pack_bf16(l0, l1); lo.y = pack_bf16(l2, l3);
}

#define AS_STRIDE 40   // 32 bf16 + 8 pad -> 80B row stride (conflict-free ldmatrix)

__global__ __launch_bounds__(256, 1) void tgemm_kernel(
    GemmJobs jobs, int M, int N, int K, int lda, int ldb, int ldc)
{
    const float* A  = jobs.A[blockIdx.z];
    const float* Bm = jobs.B[blockIdx.z];
    float*       C  = jobs.C[blockIdx.z];

    // [hi/lo][row][k]
    __shared__ __nv_bfloat16 As[2][128][AS_STRIDE];
    // [hi/lo][k][n] with XOR-16B-chunk swizzle
    __shared__ __nv_bfloat16 Bs[2][32][128];

    int tid  = threadIdx.x;
    int lane = tid & 31;
    int wid  = tid >> 5;
    int m0 = blockIdx.y * 128;
    int n0 = blockIdx.x * 128;

    int warp_m = (wid & 1) * 64;
    int warp_n = (wid >> 1) * 32;

    // A staging: 2 threads per row, 16 floats each
    int arow = tid >> 1;
    int akc  = (tid & 1) * 16;
    // B staging: 8 threads per k-row, 16 floats each
    int bk = tid >> 3;
    int bn = (tid & 7) * 16;

    float acc[4][4][4];
#pragma unroll
    for (int i = 0; i < 4; i++)
#pragma unroll
        for (int j = 0; j < 4; j++)
#pragma unroll
            for (int v = 0; v < 4; v++) acc[i][j][v] = 0.f;

    const float* Aptr = A + (long)(m0 + arow) * lda + akc;
    const float* Bptr = Bm + (long)bk * ldb + n0 + bn;

    int KT = (K + 31) / 32;
    for (int kt = 0; kt < KT; kt++) {
        int k0 = kt * 32;
        // ---- stage A ----
#pragma unroll
        for (int v = 0; v < 4; v++) {
            int kf = k0 + akc + v * 4;
            float4 f = (kf < K) ? *(const float4*)(Aptr + k0 + v * 4)
                                : make_float4(0.f, 0.f, 0.f, 0.f);
            uint2 hi, lo;
            split4(f, hi, lo);
            *(uint2*)&As[0][arow][akc + v * 4] = hi;
            *(uint2*)&As[1][arow][akc + v * 4] = lo;
        }
        // ---- stage B (swizzled) ----
        bool kok = (k0 + bk) < K;
#pragma unroll
        for (int v = 0; v < 4; v++) {
            int nf = n0 + bn + v * 4;
            float4 f = (kok && nf < N)
                           ? *(const float4*)(Bptr + (long)k0 * ldb + v * 4)
                           : make_float4(0.f, 0.f, 0.f, 0.f);
            uint2 hi, lo;
            split4(f, hi, lo);
            int e  = bn + v * 4;                 // element col in tile
            int ch = (e >> 3) ^ (bk & 7);        // swizzled 16B chunk
            int off = ch * 8 + (e & 7);
            *(uint2*)&Bs[0][bk][off] = hi;
            *(uint2*)&Bs[1][bk][off] = lo;
        }
        __syncthreads();

        // ---- compute ----
#pragma unroll
        for (int s = 0; s < 2; s++) {
            int k_off = s * 16;
            uint32_t afr[2][4][4];
            uint32_t bfr[2][4][2];
            int tileA = lane >> 3;
            int rA = (tileA & 1) * 8 + (lane & 7);
            int cA = k_off + (tileA >> 1) * 8;
#pragma unroll
            for (int h = 0; h < 2; h++)
#pragma unroll
                for (int i = 0; i < 4; i++) {
                    uint32_t addr = (uint32_t)__cvta_generic_to_shared(
                        &As[h][warp_m + i * 16 + rA][cA]);
                    ldmatrix_x4(afr[h][i], addr);
                }
            int kB = k_off + (lane & 15);
#pragma unroll
            for (int h = 0; h < 2; h++)
#pragma unroll
                for (int j = 0; j < 4; j++) {
                    int nch = (((warp_n + j * 8) >> 3) ^ (kB & 7));
                    uint32_t addr = (uint32_t)__cvta_generic_to_shared(
                        &Bs[h][kB][nch * 8]);
                    ldmatrix_x2t(bfr[h][j], addr);
                }
#pragma unroll
            for (int i = 0; i < 4; i++)
#pragma unroll
                for (int j = 0; j < 4; j++) {
                    mma_bf16(acc[i][j], afr[0][i], bfr[0][j]);
                    mma_bf16(acc[i][j], afr[0][i], bfr[1][j]);
                    mma_bf16(acc[i][j], afr[1][i], bfr[0][j]);
                }
        }
        __syncthreads();
    }

    // ---- epilogue ----
#pragma unroll
    for (int i = 0; i < 4; i++) {
        int row = m0 + warp_m + i * 16 + (lane >> 2);
#pragma unroll
        for (int j = 0; j < 4; j++) {
            int col = n0 + warp_n + j * 8 + (lane & 3) * 2;
            if (col < N) {
                *(float2*)&C[(long)row * ldc + col] =
                    make_float2(acc[i][j][0], acc[i][j][1]);
                *(float2*)&C[(long)(row + 8) * ldc + col] =
                    make_float2(acc[i][j][2], acc[i][j][3]);
            }
        }
    }
}

// ---------------------------------------------------------------------------
// GRU gate fusion per wavefront cell
// ---------------------------------------------------------------------------
struct WaveCells { int t[6]; int l[6]; };

__global__ void gate_kernel(WaveCells wc,
                            const float* __restrict__ bias_in,
                            const float* __restrict__ bias_rec)
{
    int c   = blockIdx.y;
    int idx = blockIdx.x * blockDim.x + threadIdx.x;
    if (idx >= BB * UU) return;
    int b = idx / UU;
    int u = idx - b * UU;
    int t = wc.t[c], l = wc.l[c];

    const float* xp = g_xpre + ((long)l * BT + (long)b * TT + t) * U3;
    float xz = xp[u]          + bias_in[l * U3 + u];
    float xr = xp[UU + u]     + bias_in[l * U3 + UU + u];
    float xh = xp[2 * UU + u] + bias_in[l * U3 + 2 * UU + u];

    const float* mh = g_mh + (long)c * BB * U3 + (long)b * U3;
    float hz = mh[u]          + bias_rec[l * U3 + u];
    float hr = mh[UU + u]     + bias_rec[l * U3 + UU + u];
    float hh = mh[2 * UU + u] + bias_rec[l * U3 + 2 * UU + u];

    if (l > 0) {
        const float* mx = g_mx + (long)c * BB * U3 + (long)b * U3;
        xz += mx[u];
        xr += mx[UU + u];
        xh += mx[2 * UU + u];
    }

    float h_old = g_buf[((((t + 1) & 1) * LL + l) * (long)BB + b) * UU + u];

    float z = 1.f / (1.f + expf(-(xz + hz)));
    float r = 1.f / (1.f + expf(-(xr + hr)));
    float cand = tanhf(xh + r * hh);
    float h_new = z * h_old + (1.f - z) * cand;

    g_buf[(((t & 1) * LL + l) * (long)BB + b) * UU + u] = h_new;
}

// ---------------------------------------------------------------------------
// Pack final hidden states [L][B][U] (parity 0) -> [B, L*U]
// ---------------------------------------------------------------------------
__global__ void pack_kernel()
{
    long idx = (long)blockIdx.x * blockDim.x + threadIdx.x;
    if (idx >= (long)BB * LL * UU) return;
    int b = (int)(idx / (LL * UU));
    int k = (int)(idx - (long)b * (LL * UU));
    int l = k / UU;
    int u = k - l * UU;
    g_final[idx] = g_buf[((0 * LL + l) * (long)BB + b) * UU + u];
}

// ---------------------------------------------------------------------------
// Row softmax with bias, in place on d_out [256, 32000]
// ---------------------------------------------------------------------------
__global__ void softmax_kernel(float* __restrict__ out,
                               const float* __restrict__ bias)
{
    int row = blockIdx.x;
    float* p = out + (long)row * VV;
    __shared__ float red[256];
    int tid = threadIdx.x;

    float m = -1e30f;
    for (int i = tid; i < VV; i += 256) m = fmaxf(m, p[i] + bias[i]);
    red[tid] = m; __syncthreads();
    for (int s = 128; s > 0; s >>= 1) {
        if (tid < s) red[tid] = fmaxf(red[tid], red[tid + s]);
        __syncthreads();
    }
    m = red[0]; __syncthreads();

    float sum = 0.f;
    for (int i = tid; i < VV; i += 256) {
        float e = expf(p[i] + bias[i] - m);
        p[i] = e;
        sum += e;
    }
    red[tid] = sum; __syncthreads();
    for (int s = 128; s > 0; s >>= 1) {
        if (tid < s) red[tid] += red[tid + s];
        __syncthreads();
    }
    float inv = 1.f / red[0];
    for (int i = tid; i < VV; i += 256) p[i] *= inv;
}

// ---------------------------------------------------------------------------
// Host driver
// ---------------------------------------------------------------------------
extern "C" void kernel_launch(void* const* d_in, const int* in_sizes, int n_in,
                              void* d_out, int out_size)
{
    const int*   tokens       = (const int*)  d_in[0];
    const float* init_states  = (const float*)d_in[1];
    const float* emb_table    = (const float*)d_in[2];
    const float* kernel0      = (const float*)d_in[3];
    const float* kernels_rest = (const float*)d_in[4];
    const float* rec_kernels  = (const float*)d_in[5];
    const float* bias_in      = (const float*)d_in[6];
    const float* bias_rec     = (const float*)d_in[7];
    const float* dense_kernel = (const float*)d_in[8];
    const float* dense_bias   = (const float*)d_in[9];
    float* out = (float*)d_out;

    float *p_emb, *p_xpre, *p_mh, *p_mx, *p_buf, *p_final;
    cudaGetSymbolAddress((void**)&p_emb,   g_emb);
    cudaGetSymbolAddress((void**)&p_xpre,  g_xpre);
    cudaGetSymbolAddress((void**)&p_mh,    g_mh);
    cudaGetSymbolAddress((void**)&p_mx,    g_mx);
    cudaGetSymbolAddress((void**)&p_buf,   g_buf);
    cudaGetSymbolAddress((void**)&p_final, g_final);

    // 1. embedding gather
    {
        long total = (long)BT * (EE / 4);
        embed_kernel<<<(unsigned)((total + 255) / 256), 256>>>(tokens, emb_table);
    }

    // 2. initial hidden states -> parity-1 buffer
    cudaMemcpyAsync(p_buf + (size_t)LL * BB * UU, init_states,
                    (size_t)LL * BB * UU * sizeof(float),
                    cudaMemcpyDeviceToDevice, 0);

    // 3. Xpre[l] = emb @ Kx_l for all 6 layers (batched via z)
    {
        GemmJobs jb;
        for (int l = 0; l < LL; l++) {
            jb.A[l] = p_emb;
            jb.B[l] = (l == 0) ? kernel0
                               : kernels_rest + (size_t)(l - 1) * (EE + UU) * U3;
            jb.C[l] = p_xpre + (size_t)l * BT * U3;
        }
        dim3 grid((U3 + 127) / 128, BT / 128, LL);
        tgemm_kernel<<<grid, 256>>>(jb, BT, U3, EE, EE, U3, U3);
    }

    // 4. wavefront scan over cells (t,l) with t+l = w
    for (int w = 0; w < TT + LL - 1; w++) {
        GemmJobs jb;
        WaveCells wc;
        int nj = 0, nc = 0;
        int t_lo = (w - (LL - 1) > 0) ? (w - (LL - 1)) : 0;
        int t_hi = (w < TT - 1) ? w : (TT - 1);
        for (int t = t_lo; t <= t_hi; t++) {
            int l = w - t;
            int c = nc;
            wc.t[c] = t; wc.l[c] = l;
            jb.A[nj] = p_buf + ((size_t)((t + 1) & 1) * LL + l) * BB * UU;
            jb.B[nj] = rec_kernels + (size_t)l * UU * U3;
            jb.C[nj] = p_mh + (size_t)c * BB * U3;
            nj++;
            if (l > 0) {
                jb.A[nj] = p_buf + ((size_t)(t & 1) * LL + (l - 1)) * BB * UU;
                jb.B[nj] = kernels_rest + (size_t)(l - 1) * (EE + UU) * U3
                                        + (size_t)EE * U3;
                jb.C[nj] = p_mx + (size_t)c * BB * U3;
                nj++;
            }
            nc++;
        }
        dim3 ggrid((U3 + 127) / 128, BB / 128, nj);
        tgemm_kernel<<<ggrid, 256>>>(jb, BB, U3, UU, UU, U3, U3);

        dim3 fgrid((BB * UU + 255) / 256, nc);
        gate_kernel<<<fgrid, 256>>>(wc, bias_in, bias_rec);
    }

    // 5. pack final hidden states -> [256, 6000]
    {
        long total = (long)BB * LL * UU;
        pack_kernel<<<(unsigned)((total + 255) / 256), 256>>>();
    }

    // 6. logits = final @ dense_kernel (bias added in softmax)
    {
        GemmJobs jb;
        jb.A[0] = p_final;
        jb.B[0] = dense_kernel;
        jb.C[0] = out;
        dim3 grid(VV / 128, BB / 128, 1);
        tgemm_kernel<<<grid, 256>>>(jb, BB, VV, LL * UU, LL * UU, VV, VV);
    }

    // 7. softmax rows
    softmax_kernel<<<BB, 256>>>(out, dense_bias);
}